// round 1
// baseline (speedup 1.0000x reference)
#include <cuda_runtime.h>

#define NNODES 50000
#define NEDGES_MAX 800000
#define KDIM 128
#define NHID 128
#define NCLS 40
#define BN_EPS_F 1e-5f

// ---------------- scratch (device globals; no runtime allocation) ----------
__device__ __align__(16) float g_deg[NNODES];                    // deg -> inv_deg
__device__ __align__(16) float g_agg[(size_t)NNODES * NHID];     // scatter accumulator
__device__ __align__(16) float g_h[(size_t)NNODES * NHID];       // hidden layer
__device__ int g_is64;                                           // edge dtype flag

// ---------------- edge dtype detection (int64 vs int32) --------------------
__global__ void detect_kernel(const void* eidx) {
    if (threadIdx.x == 0 && blockIdx.x == 0) {
        const long long* q = (const long long*)eidx;
        int ok = 1;
        #pragma unroll
        for (int i = 0; i < 8; ++i) {
            long long v = q[i];
            if (v < 0 || v >= NNODES) ok = 0;
        }
        g_is64 = ok;
    }
}

__device__ __forceinline__ int edge_at(const void* eidx, int i) {
    if (g_is64) return (int)((const long long*)eidx)[i];
    return ((const int*)eidx)[i];
}

// ---------------- zero / degree kernels ------------------------------------
__global__ void zero_deg_kernel() {
    int i = blockIdx.x * blockDim.x + threadIdx.x;
    if (i < NNODES) g_deg[i] = 0.0f;
}

__global__ void zero_agg_kernel() {
    int i = blockIdx.x * blockDim.x + threadIdx.x;
    if (i < NNODES * NHID) g_agg[i] = 0.0f;
}

__global__ void deg_kernel(const void* __restrict__ eidx, int E) {
    int e = blockIdx.x * blockDim.x + threadIdx.x;
    if (e >= E) return;
    int d = edge_at(eidx, E + e);   // dst row of [2, E]
    atomicAdd(&g_deg[d], 1.0f);
}

__global__ void invdeg_kernel() {
    int i = blockIdx.x * blockDim.x + threadIdx.x;
    if (i < NNODES) g_deg[i] = 1.0f / fmaxf(g_deg[i], 1.0f);
}

// ---------------- scatter-add: one warp per edge ----------------------------
// 128 floats per row: lane handles one float4 -> one red.global.add.v4.f32
template <bool FROM_H>
__global__ void scatter_kernel(const float* __restrict__ featx,
                               const void* __restrict__ eidx, int E) {
    int gw   = (blockIdx.x * blockDim.x + threadIdx.x) >> 5;
    int lane = threadIdx.x & 31;
    if (gw >= E) return;
    const float* feat = FROM_H ? (const float*)g_h : featx;
    int s = edge_at(eidx, gw);        // src
    int d = edge_at(eidx, E + gw);    // dst
    float4 v = ((const float4*)(feat + (size_t)s * KDIM))[lane];
    float* o = g_agg + (size_t)d * KDIM + (lane << 2);
    asm volatile("red.global.add.v4.f32 [%0], {%1, %2, %3, %4};"
                 :: "l"(o), "f"(v.x), "f"(v.y), "f"(v.z), "f"(v.w)
                 : "memory");
}

// ---------------- fused dual GEMM -------------------------------------------
// out = (inv_deg * agg) @ W1^T + A2 @ W2^T + bias, optional ReLU+BatchNorm.
// LAYER1: A2 = x (param), out = g_h, ReLU+BN applied.
// !LAYER1: A2 = g_h,      out = param (d_out),   plain bias.
template <int BM, int BN_T, int BK, int TM, int TN, int NOUT, bool LAYER1>
__global__ __launch_bounds__(256) void gemm_dual(
    const float* __restrict__ A2x,
    const float* __restrict__ W1, const float* __restrict__ W2,
    const float* __restrict__ bias,
    const float* __restrict__ gamma, const float* __restrict__ beta,
    const float* __restrict__ rmean, const float* __restrict__ rvar,
    float* __restrict__ outp)
{
    constexpr int K  = KDIM;
    constexpr int TX = BN_T / TN;
    constexpr int TY = BM / TM;
    constexpr int NT = TX * TY;
    static_assert(NT == 256, "thread count");

    __shared__ float As[BK][BM];
    __shared__ float Ws[BK][BN_T];

    const float* A2  = LAYER1 ? A2x : (const float*)g_h;
    float*       out = LAYER1 ? (float*)g_h : outp;

    const int tid  = threadIdx.x;
    const int tx   = tid % TX;
    const int ty   = tid / TX;
    const int row0 = blockIdx.x * BM;
    const int M    = NNODES;

    float acc[TM][TN];
    #pragma unroll
    for (int i = 0; i < TM; ++i)
        #pragma unroll
        for (int j = 0; j < TN; ++j) acc[i][j] = 0.0f;

    #pragma unroll
    for (int phase = 0; phase < 2; ++phase) {
        const float* A = phase ? A2 : (const float*)g_agg;
        const float* W = phase ? W2 : W1;

        for (int kt = 0; kt < K; kt += BK) {
            // --- load A tile (transposed, scaled by inv_deg for phase 0) ---
            #pragma unroll
            for (int i = tid; i < BM * (BK / 4); i += NT) {
                int m  = i / (BK / 4);
                int kq = i % (BK / 4);
                int row = row0 + m;
                float4 v = make_float4(0.f, 0.f, 0.f, 0.f);
                if (row < M) {
                    v = *(const float4*)(A + (size_t)row * K + kt + kq * 4);
                    if (phase == 0) {
                        float s = g_deg[row];  // holds inv_deg
                        v.x *= s; v.y *= s; v.z *= s; v.w *= s;
                    }
                }
                As[kq * 4 + 0][m] = v.x;
                As[kq * 4 + 1][m] = v.y;
                As[kq * 4 + 2][m] = v.z;
                As[kq * 4 + 3][m] = v.w;
            }
            // --- load W tile (transposed): Ws[k][n] = W[n][kt+k] ---
            #pragma unroll
            for (int i = tid; i < BN_T * (BK / 4); i += NT) {
                int n  = i / (BK / 4);
                int kq = i % (BK / 4);
                float4 v = *(const float4*)(W + (size_t)n * K + kt + kq * 4);
                Ws[kq * 4 + 0][n] = v.x;
                Ws[kq * 4 + 1][n] = v.y;
                Ws[kq * 4 + 2][n] = v.z;
                Ws[kq * 4 + 3][n] = v.w;
            }
            __syncthreads();

            #pragma unroll
            for (int k = 0; k < BK; ++k) {
                float ra[TM], rw[TN];
                #pragma unroll
                for (int i = 0; i < TM; ++i) ra[i] = As[k][ty * TM + i];
                #pragma unroll
                for (int j = 0; j < TN; ++j) rw[j] = Ws[k][tx * TN + j];
                #pragma unroll
                for (int i = 0; i < TM; ++i)
                    #pragma unroll
                    for (int j = 0; j < TN; ++j)
                        acc[i][j] = fmaf(ra[i], rw[j], acc[i][j]);
            }
            __syncthreads();
        }
    }

    // --- epilogue ---
    #pragma unroll
    for (int j = 0; j < TN; ++j) {
        int col = tx * TN + j;
        float b  = bias[col];
        float sc = 1.0f, sh = 0.0f;
        if (LAYER1) {
            sc = gamma[col] * rsqrtf(rvar[col] + BN_EPS_F);
            sh = beta[col] - rmean[col] * sc;
        }
        #pragma unroll
        for (int i = 0; i < TM; ++i) {
            int row = row0 + ty * TM + i;
            if (row < M) {
                float c = acc[i][j] + b;
                if (LAYER1) c = fmaxf(c, 0.0f) * sc + sh;
                out[(size_t)row * NOUT + col] = c;
            }
        }
    }
}

// ---------------- launch ----------------------------------------------------
extern "C" void kernel_launch(void* const* d_in, const int* in_sizes, int n_in,
                              void* d_out, int out_size) {
    const float* x     = (const float*)d_in[0];
    const void*  ei    = d_in[1];
    const float* W1l   = (const float*)d_in[2];
    const float* b1    = (const float*)d_in[3];
    const float* W1r   = (const float*)d_in[4];
    const float* gamma = (const float*)d_in[5];
    const float* beta  = (const float*)d_in[6];
    const float* rmean = (const float*)d_in[7];
    const float* rvar  = (const float*)d_in[8];
    const float* W2l   = (const float*)d_in[9];
    const float* b2    = (const float*)d_in[10];
    const float* W2r   = (const float*)d_in[11];
    float* out = (float*)d_out;

    const int E = in_sizes[1] / 2;

    detect_kernel<<<1, 32>>>(ei);
    zero_deg_kernel<<<(NNODES + 255) / 256, 256>>>();
    zero_agg_kernel<<<(NNODES * NHID + 255) / 256, 256>>>();
    deg_kernel<<<(E + 255) / 256, 256>>>(ei, E);
    invdeg_kernel<<<(NNODES + 255) / 256, 256>>>();

    // layer 1: scatter(x) -> dual GEMM + bias + ReLU + BN -> g_h
    {
        long long nthreads = (long long)E * 32;
        int blocks = (int)((nthreads + 255) / 256);
        scatter_kernel<false><<<blocks, 256>>>(x, ei, E);
    }
    gemm_dual<64, 128, 16, 8, 4, NHID, true>
        <<<(NNODES + 63) / 64, 256>>>(x, W1l, W1r, b1,
                                      gamma, beta, rmean, rvar, nullptr);

    // layer 2: re-zero agg, scatter(h) -> dual GEMM + bias -> out
    zero_agg_kernel<<<(NNODES * NHID + 255) / 256, 256>>>();
    {
        long long nthreads = (long long)E * 32;
        int blocks = (int)((nthreads + 255) / 256);
        scatter_kernel<true><<<blocks, 256>>>(x, ei, E);
    }
    gemm_dual<128, 40, 16, 4, 5, NCLS, false>
        <<<(NNODES + 127) / 128, 256>>>(x, W2l, W2r, b2,
                                        gamma, beta, rmean, rvar, out);
}

// round 3
// speedup vs baseline: 1.1916x; 1.1916x over previous
#include <cuda_runtime.h>

#define NNODES 50000
#define NEDGES_MAX 800000
#define KDIM 128
#define NHID 128
#define NCLS 40
#define BN_EPS_F 1e-5f

// ---------------- scratch (device globals; no runtime allocation) ----------
__device__ int g_is64;
__device__ int g_degi[NNODES];
__device__ int g_rowptr[NNODES];
__device__ int g_cursor[NNODES];
__device__ int g_csrc[NEDGES_MAX];
__device__ __align__(16) float g_Pl[(size_t)NNODES * NHID];  // x @ W1l^T
__device__ __align__(16) float g_Pr[(size_t)NNODES * NHID];  // x @ W1r^T
__device__ __align__(16) float g_h [(size_t)NNODES * NHID];  // hidden
__device__ __align__(16) float g_Ql[(size_t)NNODES * NCLS];  // h @ W2l^T
__device__ __align__(16) float g_Qr[(size_t)NNODES * NCLS];  // h @ W2r^T

// ---------------- edge dtype detection (int64 vs int32) --------------------
__global__ void detect_kernel(const void* eidx) {
    if (threadIdx.x == 0 && blockIdx.x == 0) {
        const long long* q = (const long long*)eidx;
        int ok = 1;
        #pragma unroll
        for (int i = 0; i < 8; ++i) {
            long long v = q[i];
            if (v < 0 || v >= NNODES) ok = 0;
        }
        g_is64 = ok;
    }
}

__device__ __forceinline__ int edge_at(const void* eidx, int i) {
    if (g_is64) return (int)((const long long*)eidx)[i];
    return ((const int*)eidx)[i];
}

// ---------------- CSR build --------------------------------------------------
__global__ void zero_degi_kernel() {
    int i = blockIdx.x * blockDim.x + threadIdx.x;
    if (i < NNODES) g_degi[i] = 0;
}

__global__ void deg_kernel(const void* __restrict__ eidx, int E) {
    int e = blockIdx.x * blockDim.x + threadIdx.x;
    if (e >= E) return;
    int d = edge_at(eidx, E + e);
    atomicAdd(&g_degi[d], 1);
}

// single-block exclusive scan over g_degi -> g_rowptr (and g_cursor copy)
__global__ __launch_bounds__(1024) void scan_kernel() {
    __shared__ int sums[1024];
    const int CH = (NNODES + 1023) / 1024;   // 49
    int t = threadIdx.x;
    int base = t * CH;
    int mysum = 0;
    for (int i = 0; i < CH; ++i) {
        int idx = base + i;
        if (idx < NNODES) mysum += g_degi[idx];
    }
    sums[t] = mysum;
    __syncthreads();
    for (int off = 1; off < 1024; off <<= 1) {
        int v = (t >= off) ? sums[t - off] : 0;
        __syncthreads();
        sums[t] += v;
        __syncthreads();
    }
    int run = sums[t] - mysum;   // exclusive prefix
    for (int i = 0; i < CH; ++i) {
        int idx = base + i;
        if (idx < NNODES) {
            g_rowptr[idx] = run;
            g_cursor[idx] = run;
            run += g_degi[idx];
        }
    }
}

__global__ void fill_kernel(const void* __restrict__ eidx, int E) {
    int e = blockIdx.x * blockDim.x + threadIdx.x;
    if (e >= E) return;
    int s = edge_at(eidx, e);
    int d = edge_at(eidx, E + e);
    int pos = atomicAdd(&g_cursor[d], 1);
    g_csrc[pos] = s;
}

// ---------------- SIMT GEMM: C = A[M,128] @ W[N,128]^T ----------------------
// STAGE 1: A = x (param),  W = blockIdx.y ? W1r : W1l,  C = g_Pr : g_Pl
// STAGE 2: A = g_h,        W = blockIdx.y ? W2r : W2l,  C = g_Qr : g_Ql
// Device globals are resolved in DEVICE code only (host cannot take their
// address — that was the R2 bug).
template <int STAGE, int BM, int BN, int BK, int TM, int TN>
__global__ __launch_bounds__(256) void gemm_tn(
    const float* __restrict__ Ax,
    const float* __restrict__ Wa, const float* __restrict__ Wb)
{
    constexpr int K  = KDIM;
    constexpr int TX = BN / TN;
    constexpr int TY = BM / TM;
    static_assert(TX * TY == 256, "thread count");
    static_assert(TY * TM == BM && TX * TN == BN, "tiling");

    __shared__ float As[BK][BM];
    __shared__ float Ws[BK][BN];

    const float* A = (STAGE == 1) ? Ax : (const float*)g_h;
    const float* W = blockIdx.y ? Wb : Wa;
    float*       C;
    if (STAGE == 1) C = blockIdx.y ? (float*)g_Pr : (float*)g_Pl;
    else            C = blockIdx.y ? (float*)g_Qr : (float*)g_Ql;

    const int tid  = threadIdx.x;
    const int tx   = tid % TX;
    const int ty   = tid / TX;
    const int row0 = blockIdx.x * BM;

    float acc[TM][TN];
    #pragma unroll
    for (int i = 0; i < TM; ++i)
        #pragma unroll
        for (int j = 0; j < TN; ++j) acc[i][j] = 0.0f;

    for (int kt = 0; kt < K; kt += BK) {
        #pragma unroll
        for (int i = tid; i < BM * (BK / 4); i += 256) {
            int m  = i / (BK / 4);
            int kq = i % (BK / 4);
            int row = row0 + m;
            float4 v = make_float4(0.f, 0.f, 0.f, 0.f);
            if (row < NNODES)
                v = *(const float4*)(A + (size_t)row * K + kt + kq * 4);
            As[kq * 4 + 0][m] = v.x;
            As[kq * 4 + 1][m] = v.y;
            As[kq * 4 + 2][m] = v.z;
            As[kq * 4 + 3][m] = v.w;
        }
        #pragma unroll
        for (int i = tid; i < BN * (BK / 4); i += 256) {
            int n  = i / (BK / 4);
            int kq = i % (BK / 4);
            float4 v = *(const float4*)(W + (size_t)n * K + kt + kq * 4);
            Ws[kq * 4 + 0][n] = v.x;
            Ws[kq * 4 + 1][n] = v.y;
            Ws[kq * 4 + 2][n] = v.z;
            Ws[kq * 4 + 3][n] = v.w;
        }
        __syncthreads();

        #pragma unroll
        for (int k = 0; k < BK; ++k) {
            float ra[TM], rw[TN];
            #pragma unroll
            for (int i = 0; i < TM; ++i) ra[i] = As[k][ty * TM + i];
            #pragma unroll
            for (int j = 0; j < TN; ++j) rw[j] = Ws[k][tx * TN + j];
            #pragma unroll
            for (int i = 0; i < TM; ++i)
                #pragma unroll
                for (int j = 0; j < TN; ++j)
                    acc[i][j] = fmaf(ra[i], rw[j], acc[i][j]);
        }
        __syncthreads();
    }

    #pragma unroll
    for (int i = 0; i < TM; ++i) {
        int row = row0 + ty * TM + i;
        if (row >= NNODES) continue;
        #pragma unroll
        for (int j = 0; j < TN; ++j)
            C[(size_t)row * BN + tx * TN + j] = acc[i][j];
    }
}

// ---------------- gather 1: h = BN(ReLU(inv*sum(Pl[nbr]) + Pr + b1)) --------
__global__ __launch_bounds__(256) void gather1_kernel(
    const float* __restrict__ b1, const float* __restrict__ gamma,
    const float* __restrict__ beta, const float* __restrict__ rmean,
    const float* __restrict__ rvar)
{
    int node = blockIdx.x * 8 + (threadIdx.x >> 5);
    if (node >= NNODES) return;
    int lane = threadIdx.x & 31;
    int start = g_rowptr[node];
    int deg   = g_degi[node];
    const float4* Pl4 = (const float4*)g_Pl;

    float4 acc = make_float4(0.f, 0.f, 0.f, 0.f);
    int i = 0;
    for (; i + 4 <= deg; i += 4) {
        int s0 = g_csrc[start + i + 0];
        int s1 = g_csrc[start + i + 1];
        int s2 = g_csrc[start + i + 2];
        int s3 = g_csrc[start + i + 3];
        float4 v0 = Pl4[(size_t)s0 * 32 + lane];
        float4 v1 = Pl4[(size_t)s1 * 32 + lane];
        float4 v2 = Pl4[(size_t)s2 * 32 + lane];
        float4 v3 = Pl4[(size_t)s3 * 32 + lane];
        acc.x += (v0.x + v1.x) + (v2.x + v3.x);
        acc.y += (v0.y + v1.y) + (v2.y + v3.y);
        acc.z += (v0.z + v1.z) + (v2.z + v3.z);
        acc.w += (v0.w + v1.w) + (v2.w + v3.w);
    }
    for (; i < deg; ++i) {
        int s = g_csrc[start + i];
        float4 v = Pl4[(size_t)s * 32 + lane];
        acc.x += v.x; acc.y += v.y; acc.z += v.z; acc.w += v.w;
    }

    float inv = 1.0f / fmaxf((float)deg, 1.0f);
    float4 pr = ((const float4*)g_Pr)[(size_t)node * 32 + lane];
    int c = lane * 4;
    float av[4] = {acc.x * inv + pr.x, acc.y * inv + pr.y,
                   acc.z * inv + pr.z, acc.w * inv + pr.w};
    float4 hv;
    float* hp = (float*)&hv;
    #pragma unroll
    for (int j = 0; j < 4; ++j) {
        int col = c + j;
        float val = fmaxf(av[j] + b1[col], 0.0f);
        float sc = gamma[col] * rsqrtf(rvar[col] + BN_EPS_F);
        hp[j] = val * sc + (beta[col] - rmean[col] * sc);
    }
    ((float4*)g_h)[(size_t)node * 32 + lane] = hv;
}

// ---------------- gather 2: out = inv*sum(Ql[nbr]) + Qr + b2 ----------------
__global__ __launch_bounds__(256) void gather2_kernel(
    const float* __restrict__ b2, float* __restrict__ out)
{
    int node = blockIdx.x * 8 + (threadIdx.x >> 5);
    if (node >= NNODES) return;
    int lane = threadIdx.x & 31;
    int start = g_rowptr[node];
    int deg   = g_degi[node];

    float a0 = 0.f, a1 = 0.f;
    int i = 0;
    for (; i + 4 <= deg; i += 4) {
        int s0 = g_csrc[start + i + 0];
        int s1 = g_csrc[start + i + 1];
        int s2 = g_csrc[start + i + 2];
        int s3 = g_csrc[start + i + 3];
        const float* r0 = g_Ql + (size_t)s0 * NCLS;
        const float* r1 = g_Ql + (size_t)s1 * NCLS;
        const float* r2 = g_Ql + (size_t)s2 * NCLS;
        const float* r3 = g_Ql + (size_t)s3 * NCLS;
        a0 += (r0[lane] + r1[lane]) + (r2[lane] + r3[lane]);
        if (lane < 8)
            a1 += (r0[32 + lane] + r1[32 + lane]) + (r2[32 + lane] + r3[32 + lane]);
    }
    for (; i < deg; ++i) {
        int s = g_csrc[start + i];
        const float* r = g_Ql + (size_t)s * NCLS;
        a0 += r[lane];
        if (lane < 8) a1 += r[32 + lane];
    }

    float inv = 1.0f / fmaxf((float)deg, 1.0f);
    const float* qr = g_Qr + (size_t)node * NCLS;
    float* o = out + (size_t)node * NCLS;
    o[lane] = a0 * inv + qr[lane] + b2[lane];
    if (lane < 8)
        o[32 + lane] = a1 * inv + qr[32 + lane] + b2[32 + lane];
}

// ---------------- launch ----------------------------------------------------
extern "C" void kernel_launch(void* const* d_in, const int* in_sizes, int n_in,
                              void* d_out, int out_size) {
    const float* x     = (const float*)d_in[0];
    const void*  ei    = d_in[1];
    const float* W1l   = (const float*)d_in[2];
    const float* b1    = (const float*)d_in[3];
    const float* W1r   = (const float*)d_in[4];
    const float* gamma = (const float*)d_in[5];
    const float* beta  = (const float*)d_in[6];
    const float* rmean = (const float*)d_in[7];
    const float* rvar  = (const float*)d_in[8];
    const float* W2l   = (const float*)d_in[9];
    const float* b2    = (const float*)d_in[10];
    const float* W2r   = (const float*)d_in[11];
    float* out = (float*)d_out;

    const int E = in_sizes[1] / 2;
    const int eb = (E + 255) / 256;

    detect_kernel<<<1, 32>>>(ei);
    zero_degi_kernel<<<(NNODES + 255) / 256, 256>>>();
    deg_kernel<<<eb, 256>>>(ei, E);
    scan_kernel<<<1, 1024>>>();
    fill_kernel<<<eb, 256>>>(ei, E);

    // P = x @ [W1l | W1r]^T   (C = g_Pl / g_Pr, resolved device-side)
    gemm_tn<1, 128, 128, 16, 8, 8>
        <<<dim3((NNODES + 127) / 128, 2), 256>>>(x, W1l, W1r);
    // h = BN(ReLU(inv_deg * agg(Pl) + Pr + b1))
    gather1_kernel<<<(NNODES + 7) / 8, 256>>>(b1, gamma, beta, rmean, rvar);
    // Q = h @ [W2l | W2r]^T   (A = g_h, C = g_Ql / g_Qr, device-side)
    gemm_tn<2, 128, 40, 16, 4, 5>
        <<<dim3((NNODES + 127) / 128, 2), 256>>>(nullptr, W2l, W2r);
    // out = inv_deg * agg(Ql) + Qr + b2
    gather2_kernel<<<(NNODES + 7) / 8, 256>>>(b2, out);
}

// round 4
// speedup vs baseline: 1.5458x; 1.2972x over previous
#include <cuda_runtime.h>

#define NNODES 50000
#define NEDGES_MAX 800000
#define KDIM 128
#define NHID 128
#define NCLS 40
#define BN_EPS_F 1e-5f

#define SCAN_B 256
#define SCAN_NB ((NNODES + SCAN_B - 1) / SCAN_B)   // 196

// ---------------- scratch (device globals; no runtime allocation) ----------
__device__ int g_is64;
__device__ int g_degi[NNODES];
__device__ int g_rowptr[NNODES];
__device__ int g_cursor[NNODES];
__device__ int g_bsum[SCAN_NB];
__device__ int g_csrc[NEDGES_MAX];
__device__ __align__(16) float g_Pl[(size_t)NNODES * NHID];  // x @ W1l^T
__device__ __align__(16) float g_Pr[(size_t)NNODES * NHID];  // x @ W1r^T
__device__ __align__(16) float g_h [(size_t)NNODES * NHID];  // hidden
__device__ __align__(16) float g_Ql[(size_t)NNODES * NCLS];  // h @ W2l^T
__device__ __align__(16) float g_Qr[(size_t)NNODES * NCLS];  // h @ W2r^T

// ---------------- edge dtype detection (int64 vs int32) --------------------
__global__ void detect_kernel(const void* eidx) {
    if (threadIdx.x == 0 && blockIdx.x == 0) {
        const long long* q = (const long long*)eidx;
        int ok = 1;
        #pragma unroll
        for (int i = 0; i < 8; ++i) {
            long long v = q[i];
            if (v < 0 || v >= NNODES) ok = 0;
        }
        g_is64 = ok;
    }
}

__device__ __forceinline__ int edge_at(const void* eidx, int i) {
    if (g_is64) return (int)((const long long*)eidx)[i];
    return ((const int*)eidx)[i];
}

// ---------------- CSR build --------------------------------------------------
__global__ void zero_degi_kernel() {
    int i = blockIdx.x * blockDim.x + threadIdx.x;
    if (i < NNODES) g_degi[i] = 0;
}

__global__ void deg_kernel(const void* __restrict__ eidx, int E) {
    int e = blockIdx.x * blockDim.x + threadIdx.x;
    if (e >= E) return;
    int d = edge_at(eidx, E + e);
    atomicAdd(&g_degi[d], 1);
}

// phase A: per-block exclusive scan; write partials + block totals
__global__ __launch_bounds__(SCAN_B) void scanA_kernel() {
    __shared__ int s[SCAN_B];
    int tid = threadIdx.x;
    int i = blockIdx.x * SCAN_B + tid;
    int v = (i < NNODES) ? g_degi[i] : 0;
    s[tid] = v;
    __syncthreads();
    #pragma unroll
    for (int off = 1; off < SCAN_B; off <<= 1) {
        int t = (tid >= off) ? s[tid - off] : 0;
        __syncthreads();
        s[tid] += t;
        __syncthreads();
    }
    if (i < NNODES) g_rowptr[i] = s[tid] - v;        // exclusive within block
    if (tid == SCAN_B - 1) g_bsum[blockIdx.x] = s[tid];
}

// phase B: single small block scans the block totals (196 values)
__global__ __launch_bounds__(SCAN_B) void scanB_kernel() {
    __shared__ int s[SCAN_B];
    int tid = threadIdx.x;
    int v = (tid < SCAN_NB) ? g_bsum[tid] : 0;
    s[tid] = v;
    __syncthreads();
    #pragma unroll
    for (int off = 1; off < SCAN_B; off <<= 1) {
        int t = (tid >= off) ? s[tid - off] : 0;
        __syncthreads();
        s[tid] += t;
        __syncthreads();
    }
    if (tid < SCAN_NB) g_bsum[tid] = s[tid] - v;      // exclusive
}

// phase C: add block offsets, copy to cursor
__global__ __launch_bounds__(SCAN_B) void scanC_kernel() {
    int i = blockIdx.x * SCAN_B + threadIdx.x;
    if (i < NNODES) {
        int r = g_rowptr[i] + g_bsum[blockIdx.x];
        g_rowptr[i] = r;
        g_cursor[i] = r;
    }
}

__global__ void fill_kernel(const void* __restrict__ eidx, int E) {
    int e = blockIdx.x * blockDim.x + threadIdx.x;
    if (e >= E) return;
    int s = edge_at(eidx, e);
    int d = edge_at(eidx, E + e);
    int pos = atomicAdd(&g_cursor[d], 1);
    g_csrc[pos] = s;
}

// ---------------- SIMT GEMM: C = A[M,128] @ W[N,128]^T ----------------------
// STAGE 1: A = x (param),  W = blockIdx.y ? W1r : W1l,  C = g_Pr : g_Pl
// STAGE 2: A = g_h,        W = blockIdx.y ? W2r : W2l,  C = g_Qr : g_Ql
template <int STAGE, int BM, int BN, int BK, int TM, int TN>
__global__ __launch_bounds__(256) void gemm_tn(
    const float* __restrict__ Ax,
    const float* __restrict__ Wa, const float* __restrict__ Wb)
{
    constexpr int K  = KDIM;
    constexpr int TX = BN / TN;
    constexpr int TY = BM / TM;
    static_assert(TX * TY == 256, "thread count");
    static_assert(TY * TM == BM && TX * TN == BN, "tiling");

    __shared__ float As[BK][BM];
    __shared__ float Ws[BK][BN];

    const float* A = (STAGE == 1) ? Ax : (const float*)g_h;
    const float* W = blockIdx.y ? Wb : Wa;
    float*       C;
    if (STAGE == 1) C = blockIdx.y ? (float*)g_Pr : (float*)g_Pl;
    else            C = blockIdx.y ? (float*)g_Qr : (float*)g_Ql;

    const int tid  = threadIdx.x;
    const int tx   = tid % TX;
    const int ty   = tid / TX;
    const int row0 = blockIdx.x * BM;

    float acc[TM][TN];
    #pragma unroll
    for (int i = 0; i < TM; ++i)
        #pragma unroll
        for (int j = 0; j < TN; ++j) acc[i][j] = 0.0f;

    for (int kt = 0; kt < K; kt += BK) {
        #pragma unroll
        for (int i = tid; i < BM * (BK / 4); i += 256) {
            int m  = i / (BK / 4);
            int kq = i % (BK / 4);
            int row = row0 + m;
            float4 v = make_float4(0.f, 0.f, 0.f, 0.f);
            if (row < NNODES)
                v = *(const float4*)(A + (size_t)row * K + kt + kq * 4);
            As[kq * 4 + 0][m] = v.x;
            As[kq * 4 + 1][m] = v.y;
            As[kq * 4 + 2][m] = v.z;
            As[kq * 4 + 3][m] = v.w;
        }
        #pragma unroll
        for (int i = tid; i < BN * (BK / 4); i += 256) {
            int n  = i / (BK / 4);
            int kq = i % (BK / 4);
            float4 v = *(const float4*)(W + (size_t)n * K + kt + kq * 4);
            Ws[kq * 4 + 0][n] = v.x;
            Ws[kq * 4 + 1][n] = v.y;
            Ws[kq * 4 + 2][n] = v.z;
            Ws[kq * 4 + 3][n] = v.w;
        }
        __syncthreads();

        #pragma unroll
        for (int k = 0; k < BK; ++k) {
            float ra[TM], rw[TN];
            #pragma unroll
            for (int i = 0; i < TM; ++i) ra[i] = As[k][ty * TM + i];
            #pragma unroll
            for (int j = 0; j < TN; ++j) rw[j] = Ws[k][tx * TN + j];
            #pragma unroll
            for (int i = 0; i < TM; ++i)
                #pragma unroll
                for (int j = 0; j < TN; ++j)
                    acc[i][j] = fmaf(ra[i], rw[j], acc[i][j]);
        }
        __syncthreads();
    }

    #pragma unroll
    for (int i = 0; i < TM; ++i) {
        int row = row0 + ty * TM + i;
        if (row >= NNODES) continue;
        #pragma unroll
        for (int j = 0; j < TN; ++j)
            C[(size_t)row * BN + tx * TN + j] = acc[i][j];
    }
}

// ---------------- gather 1: h = BN(ReLU(inv*sum(Pl[nbr]) + Pr + b1)) --------
__global__ __launch_bounds__(256) void gather1_kernel(
    const float* __restrict__ b1, const float* __restrict__ gamma,
    const float* __restrict__ beta, const float* __restrict__ rmean,
    const float* __restrict__ rvar)
{
    int node = blockIdx.x * 8 + (threadIdx.x >> 5);
    if (node >= NNODES) return;
    int lane = threadIdx.x & 31;
    int start = g_rowptr[node];
    int deg   = g_degi[node];
    const float4* Pl4 = (const float4*)g_Pl;

    float4 acc = make_float4(0.f, 0.f, 0.f, 0.f);
    int i = 0;
    for (; i + 4 <= deg; i += 4) {
        int s0 = g_csrc[start + i + 0];
        int s1 = g_csrc[start + i + 1];
        int s2 = g_csrc[start + i + 2];
        int s3 = g_csrc[start + i + 3];
        float4 v0 = Pl4[(size_t)s0 * 32 + lane];
        float4 v1 = Pl4[(size_t)s1 * 32 + lane];
        float4 v2 = Pl4[(size_t)s2 * 32 + lane];
        float4 v3 = Pl4[(size_t)s3 * 32 + lane];
        acc.x += (v0.x + v1.x) + (v2.x + v3.x);
        acc.y += (v0.y + v1.y) + (v2.y + v3.y);
        acc.z += (v0.z + v1.z) + (v2.z + v3.z);
        acc.w += (v0.w + v1.w) + (v2.w + v3.w);
    }
    for (; i < deg; ++i) {
        int s = g_csrc[start + i];
        float4 v = Pl4[(size_t)s * 32 + lane];
        acc.x += v.x; acc.y += v.y; acc.z += v.z; acc.w += v.w;
    }

    float inv = 1.0f / fmaxf((float)deg, 1.0f);
    float4 pr = ((const float4*)g_Pr)[(size_t)node * 32 + lane];
    int c = lane * 4;
    float av[4] = {acc.x * inv + pr.x, acc.y * inv + pr.y,
                   acc.z * inv + pr.z, acc.w * inv + pr.w};
    float4 hv;
    float* hp = (float*)&hv;
    #pragma unroll
    for (int j = 0; j < 4; ++j) {
        int col = c + j;
        float val = fmaxf(av[j] + b1[col], 0.0f);
        float sc = gamma[col] * rsqrtf(rvar[col] + BN_EPS_F);
        hp[j] = val * sc + (beta[col] - rmean[col] * sc);
    }
    ((float4*)g_h)[(size_t)node * 32 + lane] = hv;
}

// ---------------- gather 2: out = inv*sum(Ql[nbr]) + Qr + b2 ----------------
__global__ __launch_bounds__(256) void gather2_kernel(
    const float* __restrict__ b2, float* __restrict__ out)
{
    int node = blockIdx.x * 8 + (threadIdx.x >> 5);
    if (node >= NNODES) return;
    int lane = threadIdx.x & 31;
    int start = g_rowptr[node];
    int deg   = g_degi[node];

    float a0 = 0.f, a1 = 0.f;
    int i = 0;
    for (; i + 4 <= deg; i += 4) {
        int s0 = g_csrc[start + i + 0];
        int s1 = g_csrc[start + i + 1];
        int s2 = g_csrc[start + i + 2];
        int s3 = g_csrc[start + i + 3];
        const float* r0 = g_Ql + (size_t)s0 * NCLS;
        const float* r1 = g_Ql + (size_t)s1 * NCLS;
        const float* r2 = g_Ql + (size_t)s2 * NCLS;
        const float* r3 = g_Ql + (size_t)s3 * NCLS;
        a0 += (r0[lane] + r1[lane]) + (r2[lane] + r3[lane]);
        if (lane < 8)
            a1 += (r0[32 + lane] + r1[32 + lane]) + (r2[32 + lane] + r3[32 + lane]);
    }
    for (; i < deg; ++i) {
        int s = g_csrc[start + i];
        const float* r = g_Ql + (size_t)s * NCLS;
        a0 += r[lane];
        if (lane < 8) a1 += r[32 + lane];
    }

    float inv = 1.0f / fmaxf((float)deg, 1.0f);
    const float* qr = g_Qr + (size_t)node * NCLS;
    float* o = out + (size_t)node * NCLS;
    o[lane] = a0 * inv + qr[lane] + b2[lane];
    if (lane < 8)
        o[32 + lane] = a1 * inv + qr[32 + lane] + b2[32 + lane];
}

// ---------------- launch ----------------------------------------------------
extern "C" void kernel_launch(void* const* d_in, const int* in_sizes, int n_in,
                              void* d_out, int out_size) {
    const float* x     = (const float*)d_in[0];
    const void*  ei    = d_in[1];
    const float* W1l   = (const float*)d_in[2];
    const float* b1    = (const float*)d_in[3];
    const float* W1r   = (const float*)d_in[4];
    const float* gamma = (const float*)d_in[5];
    const float* beta  = (const float*)d_in[6];
    const float* rmean = (const float*)d_in[7];
    const float* rvar  = (const float*)d_in[8];
    const float* W2l   = (const float*)d_in[9];
    const float* b2    = (const float*)d_in[10];
    const float* W2r   = (const float*)d_in[11];
    float* out = (float*)d_out;

    const int E = in_sizes[1] / 2;
    const int eb = (E + 255) / 256;

    detect_kernel<<<1, 32>>>(ei);
    zero_degi_kernel<<<(NNODES + 255) / 256, 256>>>();
    deg_kernel<<<eb, 256>>>(ei, E);
    scanA_kernel<<<SCAN_NB, SCAN_B>>>();
    scanB_kernel<<<1, SCAN_B>>>();
    scanC_kernel<<<SCAN_NB, SCAN_B>>>();
    fill_kernel<<<eb, 256>>>(ei, E);

    // P = x @ [W1l | W1r]^T   (C = g_Pl / g_Pr, resolved device-side)
    gemm_tn<1, 128, 128, 16, 8, 8>
        <<<dim3((NNODES + 127) / 128, 2), 256>>>(x, W1l, W1r);
    // h = BN(ReLU(inv_deg * agg(Pl) + Pr + b1))
    gather1_kernel<<<(NNODES + 7) / 8, 256>>>(b1, gamma, beta, rmean, rvar);
    // Q = h @ [W2l | W2r]^T   (A = g_h, C = g_Ql / g_Qr, device-side)
    gemm_tn<2, 128, 40, 16, 4, 5>
        <<<dim3((NNODES + 127) / 128, 2), 256>>>(nullptr, W2l, W2r);
    // out = inv_deg * agg(Ql) + Qr + b2
    gather2_kernel<<<(NNODES + 7) / 8, 256>>>(b2, out);
}

// round 5
// speedup vs baseline: 2.6232x; 1.6970x over previous
#include <cuda_runtime.h>
#include <cstdint>

#define NNODES 50000
#define NEDGES_MAX 800000
#define KDIM 128
#define NHID 128
#define NCLS 40
#define BN_EPS_F 1e-5f

#define SCAN_B 256
#define SCAN_NB ((NNODES + SCAN_B - 1) / SCAN_B)   // 196

// ---------------- scratch (device globals; no runtime allocation) ----------
__device__ int g_is64;
__device__ int g_degi[NNODES];
__device__ int g_rowptr[NNODES];
__device__ int g_cursor[NNODES];
__device__ int g_bsum[SCAN_NB];
__device__ int g_csrc[NEDGES_MAX];
__device__ __align__(16) float g_Pl[(size_t)NNODES * NHID];  // x @ W1l^T
__device__ __align__(16) float g_Pr[(size_t)NNODES * NHID];  // x @ W1r^T
__device__ __align__(16) float g_h [(size_t)NNODES * NHID];  // hidden
__device__ __align__(16) float g_Ql[(size_t)NNODES * NCLS];  // h @ W2l^T
__device__ __align__(16) float g_Qr[(size_t)NNODES * NCLS];  // h @ W2r^T

// ---------------- edge dtype detection (int64 vs int32) --------------------
__global__ void detect_kernel(const void* eidx) {
    if (threadIdx.x == 0 && blockIdx.x == 0) {
        const long long* q = (const long long*)eidx;
        int ok = 1;
        #pragma unroll
        for (int i = 0; i < 8; ++i) {
            long long v = q[i];
            if (v < 0 || v >= NNODES) ok = 0;
        }
        g_is64 = ok;
    }
}

__device__ __forceinline__ int edge_at(const void* eidx, int i) {
    if (g_is64) return (int)((const long long*)eidx)[i];
    return ((const int*)eidx)[i];
}

// ---------------- CSR build --------------------------------------------------
__global__ void zero_degi_kernel() {
    int i = blockIdx.x * blockDim.x + threadIdx.x;
    if (i < NNODES) g_degi[i] = 0;
}

__global__ void deg_kernel(const void* __restrict__ eidx, int E) {
    int e = blockIdx.x * blockDim.x + threadIdx.x;
    if (e >= E) return;
    int d = edge_at(eidx, E + e);
    atomicAdd(&g_degi[d], 1);
}

__global__ __launch_bounds__(SCAN_B) void scanA_kernel() {
    __shared__ int s[SCAN_B];
    int tid = threadIdx.x;
    int i = blockIdx.x * SCAN_B + tid;
    int v = (i < NNODES) ? g_degi[i] : 0;
    s[tid] = v;
    __syncthreads();
    #pragma unroll
    for (int off = 1; off < SCAN_B; off <<= 1) {
        int t = (tid >= off) ? s[tid - off] : 0;
        __syncthreads();
        s[tid] += t;
        __syncthreads();
    }
    if (i < NNODES) g_rowptr[i] = s[tid] - v;
    if (tid == SCAN_B - 1) g_bsum[blockIdx.x] = s[tid];
}

__global__ __launch_bounds__(SCAN_B) void scanB_kernel() {
    __shared__ int s[SCAN_B];
    int tid = threadIdx.x;
    int v = (tid < SCAN_NB) ? g_bsum[tid] : 0;
    s[tid] = v;
    __syncthreads();
    #pragma unroll
    for (int off = 1; off < SCAN_B; off <<= 1) {
        int t = (tid >= off) ? s[tid - off] : 0;
        __syncthreads();
        s[tid] += t;
        __syncthreads();
    }
    if (tid < SCAN_NB) g_bsum[tid] = s[tid] - v;
}

__global__ __launch_bounds__(SCAN_B) void scanC_kernel() {
    int i = blockIdx.x * SCAN_B + threadIdx.x;
    if (i < NNODES) {
        int r = g_rowptr[i] + g_bsum[blockIdx.x];
        g_rowptr[i] = r;
        g_cursor[i] = r;
    }
}

__global__ void fill_kernel(const void* __restrict__ eidx, int E) {
    int e = blockIdx.x * blockDim.x + threadIdx.x;
    if (e >= E) return;
    int s = edge_at(eidx, e);
    int d = edge_at(eidx, E + e);
    int pos = atomicAdd(&g_cursor[d], 1);
    g_csrc[pos] = s;
}

// ---------------- tf32 tensor-core GEMM: C = A[M,128] @ W[N,128]^T ----------
__device__ __forceinline__ uint32_t to_tf32(float x) {
    uint32_t u;
    asm("cvt.rna.tf32.f32 %0, %1;" : "=r"(u) : "f"(x));
    return u;
}

__device__ __forceinline__ void mma_tf32(float* c, const uint32_t* a,
                                         uint32_t b0, uint32_t b1) {
    asm volatile(
        "mma.sync.aligned.m16n8k8.row.col.f32.tf32.tf32.f32 "
        "{%0,%1,%2,%3}, {%4,%5,%6,%7}, {%8,%9}, {%0,%1,%2,%3};"
        : "+f"(c[0]), "+f"(c[1]), "+f"(c[2]), "+f"(c[3])
        : "r"(a[0]), "r"(a[1]), "r"(a[2]), "r"(a[3]), "r"(b0), "r"(b1));
}

// STAGE 1: A = x (param),  W = blockIdx.y ? W1r : W1l,  C = g_Pr : g_Pl  (ldc 128)
// STAGE 2: A = g_h,        W = blockIdx.y ? W2r : W2l,  C = g_Qr : g_Ql  (ldc 40)
template <int STAGE, int BM, int BN, int WARPS_M, int WARPS_N>
__global__ __launch_bounds__(WARPS_M * WARPS_N * 32) void gemm_tc(
    const float* __restrict__ Ax,
    const float* __restrict__ Wa, const float* __restrict__ Wb)
{
    constexpr int BK = 32;
    constexpr int LDS_ = BK + 4;               // stride 36: conflict-free frags
    constexpr int WM = BM / WARPS_M;
    constexpr int WN = BN / WARPS_N;
    constexpr int MT = WM / 16;
    constexpr int NT = WN / 8;
    constexpr int THREADS = WARPS_M * WARPS_N * 32;
    static_assert(WM % 16 == 0 && WN % 8 == 0, "warp tile");

    __shared__ uint32_t As[BM][LDS_];
    __shared__ uint32_t Wsm[BN][LDS_];

    const float* A = (STAGE == 1) ? Ax : (const float*)g_h;
    const float* W = blockIdx.y ? Wb : Wa;
    float* C;
    int ldc;
    if (STAGE == 1) { C = blockIdx.y ? (float*)g_Pr : (float*)g_Pl; ldc = NHID; }
    else            { C = blockIdx.y ? (float*)g_Qr : (float*)g_Ql; ldc = NCLS; }

    const int tid  = threadIdx.x;
    const int warp = tid >> 5;
    const int lane = tid & 31;
    const int gid  = lane >> 2;    // 0..7
    const int tq   = lane & 3;     // 0..3
    const int wm   = (warp % WARPS_M) * WM;
    const int wn   = (warp / WARPS_M) * WN;
    const int row0 = blockIdx.x * BM;

    float acc[MT][NT][4];
    #pragma unroll
    for (int i = 0; i < MT; ++i)
        #pragma unroll
        for (int j = 0; j < NT; ++j)
            #pragma unroll
            for (int r = 0; r < 4; ++r) acc[i][j][r] = 0.0f;

    for (int kt = 0; kt < KDIM; kt += BK) {
        // load + convert A tile
        #pragma unroll
        for (int i = tid; i < BM * (BK / 4); i += THREADS) {
            int m = i / (BK / 4);
            int q = i % (BK / 4);
            int row = row0 + m;
            float4 v = make_float4(0.f, 0.f, 0.f, 0.f);
            if (row < NNODES)
                v = *(const float4*)(A + (size_t)row * KDIM + kt + q * 4);
            As[m][q * 4 + 0] = to_tf32(v.x);
            As[m][q * 4 + 1] = to_tf32(v.y);
            As[m][q * 4 + 2] = to_tf32(v.z);
            As[m][q * 4 + 3] = to_tf32(v.w);
        }
        // load + convert W tile
        #pragma unroll
        for (int i = tid; i < BN * (BK / 4); i += THREADS) {
            int n = i / (BK / 4);
            int q = i % (BK / 4);
            float4 v = *(const float4*)(W + (size_t)n * KDIM + kt + q * 4);
            Wsm[n][q * 4 + 0] = to_tf32(v.x);
            Wsm[n][q * 4 + 1] = to_tf32(v.y);
            Wsm[n][q * 4 + 2] = to_tf32(v.z);
            Wsm[n][q * 4 + 3] = to_tf32(v.w);
        }
        __syncthreads();

        #pragma unroll
        for (int ks = 0; ks < BK / 8; ++ks) {
            int k0 = ks * 8;
            uint32_t af[MT][4];
            #pragma unroll
            for (int mt = 0; mt < MT; ++mt) {
                int r = wm + mt * 16 + gid;
                af[mt][0] = As[r    ][k0 + tq];
                af[mt][1] = As[r + 8][k0 + tq];
                af[mt][2] = As[r    ][k0 + tq + 4];
                af[mt][3] = As[r + 8][k0 + tq + 4];
            }
            #pragma unroll
            for (int nt = 0; nt < NT; ++nt) {
                int n = wn + nt * 8 + gid;
                uint32_t b0 = Wsm[n][k0 + tq];
                uint32_t b1 = Wsm[n][k0 + tq + 4];
                #pragma unroll
                for (int mt = 0; mt < MT; ++mt)
                    mma_tf32(acc[mt][nt], af[mt], b0, b1);
            }
        }
        __syncthreads();
    }

    // epilogue: c0,c1 at (row, 2tq..2tq+1), c2,c3 at (row+8, ...)
    #pragma unroll
    for (int mt = 0; mt < MT; ++mt) {
        int r = row0 + wm + mt * 16 + gid;
        #pragma unroll
        for (int nt = 0; nt < NT; ++nt) {
            int c = wn + nt * 8 + 2 * tq;
            if (r < NNODES)
                *(float2*)(C + (size_t)r * ldc + c) =
                    make_float2(acc[mt][nt][0], acc[mt][nt][1]);
            if (r + 8 < NNODES)
                *(float2*)(C + (size_t)(r + 8) * ldc + c) =
                    make_float2(acc[mt][nt][2], acc[mt][nt][3]);
        }
    }
}

// ---------------- gather 1: h = BN(ReLU(inv*sum(Pl[nbr]) + Pr + b1)) --------
__global__ __launch_bounds__(256) void gather1_kernel(
    const float* __restrict__ b1, const float* __restrict__ gamma,
    const float* __restrict__ beta, const float* __restrict__ rmean,
    const float* __restrict__ rvar)
{
    int node = blockIdx.x * 8 + (threadIdx.x >> 5);
    if (node >= NNODES) return;
    int lane = threadIdx.x & 31;
    int start = g_rowptr[node];
    int deg   = g_degi[node];
    const float4* Pl4 = (const float4*)g_Pl;

    float4 acc = make_float4(0.f, 0.f, 0.f, 0.f);
    int i = 0;
    for (; i + 4 <= deg; i += 4) {
        int s0 = g_csrc[start + i + 0];
        int s1 = g_csrc[start + i + 1];
        int s2 = g_csrc[start + i + 2];
        int s3 = g_csrc[start + i + 3];
        float4 v0 = Pl4[(size_t)s0 * 32 + lane];
        float4 v1 = Pl4[(size_t)s1 * 32 + lane];
        float4 v2 = Pl4[(size_t)s2 * 32 + lane];
        float4 v3 = Pl4[(size_t)s3 * 32 + lane];
        acc.x += (v0.x + v1.x) + (v2.x + v3.x);
        acc.y += (v0.y + v1.y) + (v2.y + v3.y);
        acc.z += (v0.z + v1.z) + (v2.z + v3.z);
        acc.w += (v0.w + v1.w) + (v2.w + v3.w);
    }
    for (; i < deg; ++i) {
        int s = g_csrc[start + i];
        float4 v = Pl4[(size_t)s * 32 + lane];
        acc.x += v.x; acc.y += v.y; acc.z += v.z; acc.w += v.w;
    }

    float inv = 1.0f / fmaxf((float)deg, 1.0f);
    float4 pr = ((const float4*)g_Pr)[(size_t)node * 32 + lane];
    int c = lane * 4;
    float av[4] = {acc.x * inv + pr.x, acc.y * inv + pr.y,
                   acc.z * inv + pr.z, acc.w * inv + pr.w};
    float4 hv;
    float* hp = (float*)&hv;
    #pragma unroll
    for (int j = 0; j < 4; ++j) {
        int col = c + j;
        float val = fmaxf(av[j] + b1[col], 0.0f);
        float sc = gamma[col] * rsqrtf(rvar[col] + BN_EPS_F);
        hp[j] = val * sc + (beta[col] - rmean[col] * sc);
    }
    ((float4*)g_h)[(size_t)node * 32 + lane] = hv;
}

// ---------------- gather 2: out = inv*sum(Ql[nbr]) + Qr + b2 ----------------
__global__ __launch_bounds__(256) void gather2_kernel(
    const float* __restrict__ b2, float* __restrict__ out)
{
    int node = blockIdx.x * 8 + (threadIdx.x >> 5);
    if (node >= NNODES) return;
    int lane = threadIdx.x & 31;
    int start = g_rowptr[node];
    int deg   = g_degi[node];

    float a0 = 0.f, a1 = 0.f;
    int i = 0;
    for (; i + 4 <= deg; i += 4) {
        int s0 = g_csrc[start + i + 0];
        int s1 = g_csrc[start + i + 1];
        int s2 = g_csrc[start + i + 2];
        int s3 = g_csrc[start + i + 3];
        const float* r0 = g_Ql + (size_t)s0 * NCLS;
        const float* r1 = g_Ql + (size_t)s1 * NCLS;
        const float* r2 = g_Ql + (size_t)s2 * NCLS;
        const float* r3 = g_Ql + (size_t)s3 * NCLS;
        a0 += (r0[lane] + r1[lane]) + (r2[lane] + r3[lane]);
        if (lane < 8)
            a1 += (r0[32 + lane] + r1[32 + lane]) + (r2[32 + lane] + r3[32 + lane]);
    }
    for (; i < deg; ++i) {
        int s = g_csrc[start + i];
        const float* r = g_Ql + (size_t)s * NCLS;
        a0 += r[lane];
        if (lane < 8) a1 += r[32 + lane];
    }

    float inv = 1.0f / fmaxf((float)deg, 1.0f);
    const float* qr = g_Qr + (size_t)node * NCLS;
    float* o = out + (size_t)node * NCLS;
    o[lane] = a0 * inv + qr[lane] + b2[lane];
    if (lane < 8)
        o[32 + lane] = a1 * inv + qr[32 + lane] + b2[32 + lane];
}

// ---------------- launch ----------------------------------------------------
extern "C" void kernel_launch(void* const* d_in, const int* in_sizes, int n_in,
                              void* d_out, int out_size) {
    const float* x     = (const float*)d_in[0];
    const void*  ei    = d_in[1];
    const float* W1l   = (const float*)d_in[2];
    const float* b1    = (const float*)d_in[3];
    const float* W1r   = (const float*)d_in[4];
    const float* gamma = (const float*)d_in[5];
    const float* beta  = (const float*)d_in[6];
    const float* rmean = (const float*)d_in[7];
    const float* rvar  = (const float*)d_in[8];
    const float* W2l   = (const float*)d_in[9];
    const float* b2    = (const float*)d_in[10];
    const float* W2r   = (const float*)d_in[11];
    float* out = (float*)d_out;

    const int E = in_sizes[1] / 2;
    const int eb = (E + 255) / 256;

    detect_kernel<<<1, 32>>>(ei);
    zero_degi_kernel<<<(NNODES + 255) / 256, 256>>>();
    deg_kernel<<<eb, 256>>>(ei, E);
    scanA_kernel<<<SCAN_NB, SCAN_B>>>();
    scanB_kernel<<<1, SCAN_B>>>();
    scanC_kernel<<<SCAN_NB, SCAN_B>>>();
    fill_kernel<<<eb, 256>>>(ei, E);

    // P = x @ [W1l | W1r]^T   (tensor cores, tf32)
    gemm_tc<1, 128, 128, 4, 2>
        <<<dim3((NNODES + 127) / 128, 2), 256>>>(x, W1l, W1r);
    // h = BN(ReLU(inv_deg * agg(Pl) + Pr + b1))
    gather1_kernel<<<(NNODES + 7) / 8, 256>>>(b1, gamma, beta, rmean, rvar);
    // Q = h @ [W2l | W2r]^T   (tensor cores, tf32)
    gemm_tc<2, 128, 40, 8, 1>
        <<<dim3((NNODES + 127) / 128, 2), 256>>>(nullptr, W2l, W2r);
    // out = inv_deg * agg(Ql) + Qr + b2
    gather2_kernel<<<(NNODES + 7) / 8, 256>>>(b2, out);
}

// round 6
// speedup vs baseline: 2.7862x; 1.0621x over previous
#include <cuda_runtime.h>
#include <cuda_fp16.h>
#include <cstdint>

#define NNODES 50000
#define NEDGES_MAX 800000
#define KDIM 128
#define NHID 128
#define NCLS 40
#define BN_EPS_F 1e-5f

#define SCAN_B 256
#define SCAN_NB ((NNODES + SCAN_B - 1) / SCAN_B)   // 196
#define EPT 8   // edges per thread in CSR-build kernels

// ---------------- scratch (device globals; no runtime allocation) ----------
__device__ int g_is64;
__device__ int g_degi[NNODES];
__device__ int g_rowptr[NNODES];
__device__ int g_cursor[NNODES];
__device__ int g_bsum[SCAN_NB];
__device__ int g_csrc[NEDGES_MAX];
__device__ __align__(16) __half2 g_Plh[(size_t)NNODES * (NHID / 2)]; // x @ W1l^T (fp16)
__device__ __align__(16) float g_Pr[(size_t)NNODES * NHID];  // x @ W1r^T
__device__ __align__(16) float g_h [(size_t)NNODES * NHID];  // hidden
__device__ __align__(16) float g_Ql[(size_t)NNODES * NCLS];  // h @ W2l^T
__device__ __align__(16) float g_Qr[(size_t)NNODES * NCLS];  // h @ W2r^T

// ---------------- edge dtype detection (int64 vs int32) --------------------
__global__ void detect_kernel(const void* eidx) {
    if (threadIdx.x == 0 && blockIdx.x == 0) {
        const long long* q = (const long long*)eidx;
        int ok = 1;
        #pragma unroll
        for (int i = 0; i < 8; ++i) {
            long long v = q[i];
            if (v < 0 || v >= NNODES) ok = 0;
        }
        g_is64 = ok;
    }
}

__device__ __forceinline__ int edge_at(const void* eidx, int i) {
    if (g_is64) return (int)((const long long*)eidx)[i];
    return ((const int*)eidx)[i];
}

// ---------------- CSR build --------------------------------------------------
__global__ void zero_degi_kernel() {
    int i = blockIdx.x * blockDim.x + threadIdx.x;
    if (i < NNODES) g_degi[i] = 0;
}

// 8 edges/thread: front-batch the index loads (MLP=8), then fire the REDs.
__global__ void deg_kernel(const void* __restrict__ eidx, int E) {
    int base = (blockIdx.x * blockDim.x + threadIdx.x) * EPT;
    int d[EPT];
    #pragma unroll
    for (int j = 0; j < EPT; ++j) {
        int e = base + j;
        d[j] = (e < E) ? edge_at(eidx, E + e) : -1;
    }
    #pragma unroll
    for (int j = 0; j < EPT; ++j)
        if (d[j] >= 0) atomicAdd(&g_degi[d[j]], 1);
}

__global__ __launch_bounds__(SCAN_B) void scanA_kernel() {
    __shared__ int s[SCAN_B];
    int tid = threadIdx.x;
    int i = blockIdx.x * SCAN_B + tid;
    int v = (i < NNODES) ? g_degi[i] : 0;
    s[tid] = v;
    __syncthreads();
    #pragma unroll
    for (int off = 1; off < SCAN_B; off <<= 1) {
        int t = (tid >= off) ? s[tid - off] : 0;
        __syncthreads();
        s[tid] += t;
        __syncthreads();
    }
    if (i < NNODES) g_rowptr[i] = s[tid] - v;
    if (tid == SCAN_B - 1) g_bsum[blockIdx.x] = s[tid];
}

__global__ __launch_bounds__(SCAN_B) void scanB_kernel() {
    __shared__ int s[SCAN_B];
    int tid = threadIdx.x;
    int v = (tid < SCAN_NB) ? g_bsum[tid] : 0;
    s[tid] = v;
    __syncthreads();
    #pragma unroll
    for (int off = 1; off < SCAN_B; off <<= 1) {
        int t = (tid >= off) ? s[tid - off] : 0;
        __syncthreads();
        s[tid] += t;
        __syncthreads();
    }
    if (tid < SCAN_NB) g_bsum[tid] = s[tid] - v;
}

__global__ __launch_bounds__(SCAN_B) void scanC_kernel() {
    int i = blockIdx.x * SCAN_B + threadIdx.x;
    if (i < NNODES) {
        int r = g_rowptr[i] + g_bsum[blockIdx.x];
        g_rowptr[i] = r;
        g_cursor[i] = r;
    }
}

__global__ void fill_kernel(const void* __restrict__ eidx, int E) {
    int base = (blockIdx.x * blockDim.x + threadIdx.x) * EPT;
    int s[EPT], d[EPT];
    #pragma unroll
    for (int j = 0; j < EPT; ++j) {
        int e = base + j;
        if (e < E) { s[j] = edge_at(eidx, e); d[j] = edge_at(eidx, E + e); }
        else       { s[j] = -1; d[j] = 0; }
    }
    #pragma unroll
    for (int j = 0; j < EPT; ++j) {
        if (s[j] >= 0) {
            int pos = atomicAdd(&g_cursor[d[j]], 1);
            g_csrc[pos] = s[j];
        }
    }
}

// ---------------- tf32 tensor-core GEMM: C = A[M,128] @ W[N,128]^T ----------
__device__ __forceinline__ uint32_t to_tf32(float x) {
    uint32_t u;
    asm("cvt.rna.tf32.f32 %0, %1;" : "=r"(u) : "f"(x));
    return u;
}

__device__ __forceinline__ void mma_tf32(float* c, const uint32_t* a,
                                         uint32_t b0, uint32_t b1) {
    asm volatile(
        "mma.sync.aligned.m16n8k8.row.col.f32.tf32.tf32.f32 "
        "{%0,%1,%2,%3}, {%4,%5,%6,%7}, {%8,%9}, {%0,%1,%2,%3};"
        : "+f"(c[0]), "+f"(c[1]), "+f"(c[2]), "+f"(c[3])
        : "r"(a[0]), "r"(a[1]), "r"(a[2]), "r"(a[3]), "r"(b0), "r"(b1));
}

// STAGE 1: A = x,    W = y? W1r : W1l,  C = y? g_Pr(f32) : g_Plh(fp16)
// STAGE 2: A = g_h,  W = y? W2r : W2l,  C = y? g_Qr : g_Ql (f32, ldc 40)
template <int STAGE, int BM, int BN, int WARPS_M, int WARPS_N>
__global__ __launch_bounds__(WARPS_M * WARPS_N * 32) void gemm_tc(
    const float* __restrict__ Ax,
    const float* __restrict__ Wa, const float* __restrict__ Wb)
{
    constexpr int BK = 32;
    constexpr int LDS_ = BK + 4;               // stride 36: conflict-free frags
    constexpr int WM = BM / WARPS_M;
    constexpr int WN = BN / WARPS_N;
    constexpr int MT = WM / 16;
    constexpr int NT = WN / 8;
    constexpr int THREADS = WARPS_M * WARPS_N * 32;
    static_assert(WM % 16 == 0 && WN % 8 == 0, "warp tile");

    __shared__ uint32_t As[BM][LDS_];
    __shared__ uint32_t Wsm[BN][LDS_];

    const float* A = (STAGE == 1) ? Ax : (const float*)g_h;
    const float* W = blockIdx.y ? Wb : Wa;

    const int tid  = threadIdx.x;
    const int warp = tid >> 5;
    const int lane = tid & 31;
    const int gid  = lane >> 2;    // 0..7
    const int tq   = lane & 3;     // 0..3
    const int wm   = (warp % WARPS_M) * WM;
    const int wn   = (warp / WARPS_M) * WN;
    const int row0 = blockIdx.x * BM;

    float acc[MT][NT][4];
    #pragma unroll
    for (int i = 0; i < MT; ++i)
        #pragma unroll
        for (int j = 0; j < NT; ++j)
            #pragma unroll
            for (int r = 0; r < 4; ++r) acc[i][j][r] = 0.0f;

    for (int kt = 0; kt < KDIM; kt += BK) {
        #pragma unroll
        for (int i = tid; i < BM * (BK / 4); i += THREADS) {
            int m = i / (BK / 4);
            int q = i % (BK / 4);
            int row = row0 + m;
            float4 v = make_float4(0.f, 0.f, 0.f, 0.f);
            if (row < NNODES)
                v = *(const float4*)(A + (size_t)row * KDIM + kt + q * 4);
            As[m][q * 4 + 0] = to_tf32(v.x);
            As[m][q * 4 + 1] = to_tf32(v.y);
            As[m][q * 4 + 2] = to_tf32(v.z);
            As[m][q * 4 + 3] = to_tf32(v.w);
        }
        #pragma unroll
        for (int i = tid; i < BN * (BK / 4); i += THREADS) {
            int n = i / (BK / 4);
            int q = i % (BK / 4);
            float4 v = *(const float4*)(W + (size_t)n * KDIM + kt + q * 4);
            Wsm[n][q * 4 + 0] = to_tf32(v.x);
            Wsm[n][q * 4 + 1] = to_tf32(v.y);
            Wsm[n][q * 4 + 2] = to_tf32(v.z);
            Wsm[n][q * 4 + 3] = to_tf32(v.w);
        }
        __syncthreads();

        #pragma unroll
        for (int ks = 0; ks < BK / 8; ++ks) {
            int k0 = ks * 8;
            uint32_t af[MT][4];
            #pragma unroll
            for (int mt = 0; mt < MT; ++mt) {
                int r = wm + mt * 16 + gid;
                af[mt][0] = As[r    ][k0 + tq];
                af[mt][1] = As[r + 8][k0 + tq];
                af[mt][2] = As[r    ][k0 + tq + 4];
                af[mt][3] = As[r + 8][k0 + tq + 4];
            }
            #pragma unroll
            for (int nt = 0; nt < NT; ++nt) {
                int n = wn + nt * 8 + gid;
                uint32_t b0 = Wsm[n][k0 + tq];
                uint32_t b1 = Wsm[n][k0 + tq + 4];
                #pragma unroll
                for (int mt = 0; mt < MT; ++mt)
                    mma_tf32(acc[mt][nt], af[mt], b0, b1);
            }
        }
        __syncthreads();
    }

    // epilogue: c0,c1 at (row, 2tq..2tq+1), c2,c3 at (row+8, ...)
    const bool to_half = (STAGE == 1) && (blockIdx.y == 0);
    float* C;
    int ldc;
    if (STAGE == 1) { C = (float*)g_Pr; ldc = NHID; }
    else            { C = blockIdx.y ? (float*)g_Qr : (float*)g_Ql; ldc = NCLS; }

    #pragma unroll
    for (int mt = 0; mt < MT; ++mt) {
        int r = row0 + wm + mt * 16 + gid;
        #pragma unroll
        for (int nt = 0; nt < NT; ++nt) {
            int c = wn + nt * 8 + 2 * tq;
            if (to_half) {
                if (r < NNODES)
                    g_Plh[(size_t)r * (NHID / 2) + c / 2] =
                        __floats2half2_rn(acc[mt][nt][0], acc[mt][nt][1]);
                if (r + 8 < NNODES)
                    g_Plh[(size_t)(r + 8) * (NHID / 2) + c / 2] =
                        __floats2half2_rn(acc[mt][nt][2], acc[mt][nt][3]);
            } else {
                if (r < NNODES)
                    *(float2*)(C + (size_t)r * ldc + c) =
                        make_float2(acc[mt][nt][0], acc[mt][nt][1]);
                if (r + 8 < NNODES)
                    *(float2*)(C + (size_t)(r + 8) * ldc + c) =
                        make_float2(acc[mt][nt][2], acc[mt][nt][3]);
            }
        }
    }
}

// ---------------- gather 1: h = BN(ReLU(inv*sum(Plh[nbr]) + Pr + b1)) -------
// Pl is fp16: lane loads 8B (2×half2 = 4 cols) per neighbor row.
__global__ __launch_bounds__(256) void gather1_kernel(
    const float* __restrict__ b1, const float* __restrict__ gamma,
    const float* __restrict__ beta, const float* __restrict__ rmean,
    const float* __restrict__ rvar)
{
    int node = blockIdx.x * 8 + (threadIdx.x >> 5);
    if (node >= NNODES) return;
    int lane = threadIdx.x & 31;
    int start = g_rowptr[node];
    int deg   = g_degi[node];
    const __half2* Pl2 = g_Plh;

    float4 acc = make_float4(0.f, 0.f, 0.f, 0.f);
    int i = 0;
    for (; i + 4 <= deg; i += 4) {
        int s0 = g_csrc[start + i + 0];
        int s1 = g_csrc[start + i + 1];
        int s2 = g_csrc[start + i + 2];
        int s3 = g_csrc[start + i + 3];
        uint2 u0 = *(const uint2*)(Pl2 + (size_t)s0 * 64 + lane * 2);
        uint2 u1 = *(const uint2*)(Pl2 + (size_t)s1 * 64 + lane * 2);
        uint2 u2 = *(const uint2*)(Pl2 + (size_t)s2 * 64 + lane * 2);
        uint2 u3 = *(const uint2*)(Pl2 + (size_t)s3 * 64 + lane * 2);
        #pragma unroll
        for (int t = 0; t < 4; ++t) {
            uint2 u = (t == 0) ? u0 : (t == 1) ? u1 : (t == 2) ? u2 : u3;
            float2 a = __half22float2(*(const __half2*)&u.x);
            float2 b = __half22float2(*(const __half2*)&u.y);
            acc.x += a.x; acc.y += a.y; acc.z += b.x; acc.w += b.y;
        }
    }
    for (; i < deg; ++i) {
        int s = g_csrc[start + i];
        uint2 u = *(const uint2*)(Pl2 + (size_t)s * 64 + lane * 2);
        float2 a = __half22float2(*(const __half2*)&u.x);
        float2 b = __half22float2(*(const __half2*)&u.y);
        acc.x += a.x; acc.y += a.y; acc.z += b.x; acc.w += b.y;
    }

    float inv = 1.0f / fmaxf((float)deg, 1.0f);
    float4 pr = ((const float4*)g_Pr)[(size_t)node * 32 + lane];
    int c = lane * 4;
    float av[4] = {acc.x * inv + pr.x, acc.y * inv + pr.y,
                   acc.z * inv + pr.z, acc.w * inv + pr.w};
    float4 hv;
    float* hp = (float*)&hv;
    #pragma unroll
    for (int j = 0; j < 4; ++j) {
        int col = c + j;
        float val = fmaxf(av[j] + b1[col], 0.0f);
        float sc = gamma[col] * rsqrtf(rvar[col] + BN_EPS_F);
        hp[j] = val * sc + (beta[col] - rmean[col] * sc);
    }
    ((float4*)g_h)[(size_t)node * 32 + lane] = hv;
}

// ---------------- gather 2: out = inv*sum(Ql[nbr]) + Qr + b2 ----------------
__global__ __launch_bounds__(256) void gather2_kernel(
    const float* __restrict__ b2, float* __restrict__ out)
{
    int node = blockIdx.x * 8 + (threadIdx.x >> 5);
    if (node >= NNODES) return;
    int lane = threadIdx.x & 31;
    int start = g_rowptr[node];
    int deg   = g_degi[node];

    float a0 = 0.f, a1 = 0.f;
    int i = 0;
    for (; i + 4 <= deg; i += 4) {
        int s0 = g_csrc[start + i + 0];
        int s1 = g_csrc[start + i + 1];
        int s2 = g_csrc[start + i + 2];
        int s3 = g_csrc[start + i + 3];
        const float* r0 = g_Ql + (size_t)s0 * NCLS;
        const float* r1 = g_Ql + (size_t)s1 * NCLS;
        const float* r2 = g_Ql + (size_t)s2 * NCLS;
        const float* r3 = g_Ql + (size_t)s3 * NCLS;
        a0 += (r0[lane] + r1[lane]) + (r2[lane] + r3[lane]);
        if (lane < 8)
            a1 += (r0[32 + lane] + r1[32 + lane]) + (r2[32 + lane] + r3[32 + lane]);
    }
    for (; i < deg; ++i) {
        int s = g_csrc[start + i];
        const float* r = g_Ql + (size_t)s * NCLS;
        a0 += r[lane];
        if (lane < 8) a1 += r[32 + lane];
    }

    float inv = 1.0f / fmaxf((float)deg, 1.0f);
    const float* qr = g_Qr + (size_t)node * NCLS;
    float* o = out + (size_t)node * NCLS;
    o[lane] = a0 * inv + qr[lane] + b2[lane];
    if (lane < 8)
        o[32 + lane] = a1 * inv + qr[32 + lane] + b2[32 + lane];
}

// ---------------- launch ----------------------------------------------------
extern "C" void kernel_launch(void* const* d_in, const int* in_sizes, int n_in,
                              void* d_out, int out_size) {
    const float* x     = (const float*)d_in[0];
    const void*  ei    = d_in[1];
    const float* W1l   = (const float*)d_in[2];
    const float* b1    = (const float*)d_in[3];
    const float* W1r   = (const float*)d_in[4];
    const float* gamma = (const float*)d_in[5];
    const float* beta  = (const float*)d_in[6];
    const float* rmean = (const float*)d_in[7];
    const float* rvar  = (const float*)d_in[8];
    const float* W2l   = (const float*)d_in[9];
    const float* b2    = (const float*)d_in[10];
    const float* W2r   = (const float*)d_in[11];
    float* out = (float*)d_out;

    const int E = in_sizes[1] / 2;
    const int ebatch = (E + 256 * EPT - 1) / (256 * EPT);

    detect_kernel<<<1, 32>>>(ei);
    zero_degi_kernel<<<(NNODES + 255) / 256, 256>>>();
    deg_kernel<<<ebatch, 256>>>(ei, E);
    scanA_kernel<<<SCAN_NB, SCAN_B>>>();
    scanB_kernel<<<1, SCAN_B>>>();
    scanC_kernel<<<SCAN_NB, SCAN_B>>>();
    fill_kernel<<<ebatch, 256>>>(ei, E);

    // P = x @ [W1l | W1r]^T   (tensor cores, tf32; Pl stored fp16)
    gemm_tc<1, 128, 128, 4, 2>
        <<<dim3((NNODES + 127) / 128, 2), 256>>>(x, W1l, W1r);
    // h = BN(ReLU(inv_deg * agg(Pl) + Pr + b1))
    gather1_kernel<<<(NNODES + 7) / 8, 256>>>(b1, gamma, beta, rmean, rvar);
    // Q = h @ [W2l | W2r]^T   (tensor cores, tf32)
    gemm_tc<2, 128, 40, 8, 1>
        <<<dim3((NNODES + 127) / 128, 2), 256>>>(nullptr, W2l, W2r);
    // out = inv_deg * agg(Ql) + Qr + b2
    gather2_kernel<<<(NNODES + 7) / 8, 256>>>(b2, out);
}